// round 3
// baseline (speedup 1.0000x reference)
#include <cuda_runtime.h>
#include <math.h>

#define B_SZ 512
#define NV_EN 30000
#define NV_CN 20000
#define KT 100
#define HD 512
#define DE 300
#define TAU_ 1.0f
#define EPS_SK 0.1f

typedef unsigned long long ull;

// ---------------- device scratch (static, no allocations, 16B-aligned) ----------------
__device__ __align__(16) float g_h1[B_SZ * HD];
__device__ __align__(16) float g_h2[B_SZ * HD];
__device__ __align__(16) float g_mu[B_SZ * KT];
__device__ __align__(16) float g_lv[B_SZ * KT];
__device__ __align__(16) float g_G[NV_EN * KT];       // word-topic dot products (reused en/cn)
__device__ __align__(16) float g_beta[KT * NV_EN];    // aligned beta copy (GEMM operand)
__device__ __align__(16) float g_recon[B_SZ * NV_EN]; // reconstruction scratch (reused en/cn)
__device__ __align__(16) float g_theta_en[B_SZ * KT];
__device__ __align__(16) float g_theta_cn[B_SZ * KT];
__device__ __align__(16) float g_wnorm[NV_EN];
__device__ __align__(16) float g_tnorm[KT];
__device__ __align__(16) float g_topicT[DE * KT];
__device__ __align__(16) float g_tn[B_SZ * KT];       // normalized selected thetas
__device__ __align__(16) float g_tnT[KT * DE];        // normalized topic embeddings
__device__ __align__(16) float g_C[KT * KT];
__device__ __align__(16) float g_colsum[KT];
__device__ __align__(16) float g_acc[8]; // 0:rec_en 1:kl_en 2:rec_cn 3:kl_cn 4:closs 5:ccnt 6:align

// ---------------- fp32 GEMM via packed fma.rn.f32x2: C = A[MxK] @ B[KxN] ----------------
// BM=BN=128, BK=16, 256 threads, 8x8 microtile as 8x(4 pairs).
// A tile stored DUPLICATED in shared: As2[kk][2m]=As2[kk][2m+1]=A[row,kk]
// so the broadcast operand of fma.rn.f32x2 loads directly as LDS.64 (no pack MOVs).
// mode 0: store, 1: atomicAdd (split-K). REQUIRES: A, B 16-byte aligned; K % 4 == 0.
__global__ __launch_bounds__(256, 2)
void gemm128(const float* __restrict__ A, const float* __restrict__ B,
             float* __restrict__ C, int M, int N, int K,
             int kStepsPerZ, int mode)
{
    __shared__ __align__(16) float As2[16][258];  // duplicated A, padded row (bank-conflict-free stores)
    __shared__ __align__(16) float Bs[16][128];
    int tid = threadIdx.x;
    int row0 = blockIdx.y * 128;
    int col0 = blockIdx.x * 128;
    int kStart = blockIdx.z * kStepsPerZ * 16;
    if (kStart >= K) return;
    int kEnd = min(K, kStart + kStepsPerZ * 16);

    ull acc2[8][4];
#pragma unroll
    for (int i = 0; i < 8; i++)
#pragma unroll
        for (int p = 0; p < 4; p++) acc2[i][p] = 0ull;

    int tx = tid & 15, ty = tid >> 4;

    for (int k0 = kStart; k0 < kEnd; k0 += 16) {
        // load A tile 128x16 (float4), store duplicated pairs into As2[kk][2m..2m+1]
#pragma unroll
        for (int s = 0; s < 2; s++) {
            int lin = tid + s * 256;
            int m = lin >> 2;
            int kk = (lin & 3) * 4;
            int row = row0 + m;
            int gk = k0 + kk;
            float4 v = make_float4(0.f, 0.f, 0.f, 0.f);
            if (row < M && gk < kEnd)
                v = *reinterpret_cast<const float4*>(&A[(size_t)row * K + gk]);
            *reinterpret_cast<float2*>(&As2[kk + 0][2 * m]) = make_float2(v.x, v.x);
            *reinterpret_cast<float2*>(&As2[kk + 1][2 * m]) = make_float2(v.y, v.y);
            *reinterpret_cast<float2*>(&As2[kk + 2][2 * m]) = make_float2(v.z, v.z);
            *reinterpret_cast<float2*>(&As2[kk + 3][2 * m]) = make_float2(v.w, v.w);
        }
        // load B tile 16x128 (float4)
#pragma unroll
        for (int s = 0; s < 2; s++) {
            int lin = tid + s * 256;
            int kk = lin >> 5;
            int n = (lin & 31) * 4;
            int gk = k0 + kk;
            int col = col0 + n;
            float4 v = make_float4(0.f, 0.f, 0.f, 0.f);
            if (gk < kEnd && col + 3 < N)
                v = *reinterpret_cast<const float4*>(&B[(size_t)gk * N + col]);
            else if (gk < kEnd) {
                if (col + 0 < N) v.x = B[(size_t)gk * N + col + 0];
                if (col + 1 < N) v.y = B[(size_t)gk * N + col + 1];
                if (col + 2 < N) v.z = B[(size_t)gk * N + col + 2];
                if (col + 3 < N) v.w = B[(size_t)gk * N + col + 3];
            }
            *reinterpret_cast<float4*>(&Bs[kk][n]) = v;
        }
        __syncthreads();
#pragma unroll
        for (int kk = 0; kk < 16; kk++) {
            ull a2[8], b2[4];
#pragma unroll
            for (int i = 0; i < 8; i++)
                a2[i] = *reinterpret_cast<const ull*>(&As2[kk][ty * 16 + 2 * i]);
#pragma unroll
            for (int p = 0; p < 4; p++)
                b2[p] = *reinterpret_cast<const ull*>(&Bs[kk][tx * 8 + 2 * p]);
#pragma unroll
            for (int i = 0; i < 8; i++)
#pragma unroll
                for (int p = 0; p < 4; p++)
                    asm("fma.rn.f32x2 %0, %1, %2, %0;"
                        : "+l"(acc2[i][p]) : "l"(a2[i]), "l"(b2[p]));
        }
        __syncthreads();
    }

#pragma unroll
    for (int i = 0; i < 8; i++) {
        int row = row0 + ty * 8 + i;
        if (row >= M) continue;
#pragma unroll
        for (int p = 0; p < 4; p++) {
            float2 f = *reinterpret_cast<float2*>(&acc2[i][p]);
            int col = col0 + tx * 8 + 2 * p;
            if (col < N) {
                if (mode == 0) C[(size_t)row * N + col] = f.x;
                else atomicAdd(&C[(size_t)row * N + col], f.x);
            }
            if (col + 1 < N) {
                if (mode == 0) C[(size_t)row * N + col + 1] = f.y;
                else atomicAdd(&C[(size_t)row * N + col + 1], f.y);
            }
        }
    }
}

// ---------------- elementwise helpers ----------------
__global__ void zero_kernel(float* p, int n) {
    for (int i = blockIdx.x * blockDim.x + threadIdx.x; i < n; i += gridDim.x * blockDim.x)
        p[i] = 0.f;
}

__global__ void bias_softplus(float* X, const float* __restrict__ bias, int M, int N) {
    int total = M * N;
    for (int idx = blockIdx.x * blockDim.x + threadIdx.x; idx < total; idx += gridDim.x * blockDim.x) {
        int j = idx % N;
        float v = X[idx] + bias[j];
        X[idx] = fmaxf(v, 0.f) + log1pf(expf(-fabsf(v)));
    }
}

// ---------------- z + softmax + KL (fused, one block per row) ----------------
__global__ void theta_kl_kernel(const float* __restrict__ mu_raw, const float* __restrict__ lv_raw,
                                const float* __restrict__ bmu, const float* __restrict__ blv,
                                const float* __restrict__ eps, float* __restrict__ theta_scratch,
                                float* __restrict__ theta_dout, float* kl_acc)
{
    int i = blockIdx.x;
    int k = threadIdx.x; // 128
    __shared__ float red[128];
    float zv = -1e30f, kl = 0.f;
    if (k < KT) {
        float mu = mu_raw[i * KT + k] + bmu[k];
        float lv = lv_raw[i * KT + k] + blv[k];
        zv = mu + eps[i * KT + k] * expf(0.5f * lv);
        kl = expf(lv) + mu * mu - 1.f - lv;
    }
    red[k] = zv; __syncthreads();
    for (int s = 64; s > 0; s >>= 1) { if (k < s) red[k] = fmaxf(red[k], red[k + s]); __syncthreads(); }
    float m = red[0]; __syncthreads();
    float e = (k < KT) ? expf(zv - m) : 0.f;
    red[k] = e; __syncthreads();
    for (int s = 64; s > 0; s >>= 1) { if (k < s) red[k] += red[k + s]; __syncthreads(); }
    float ssum = red[0]; __syncthreads();
    if (k < KT) {
        float t = e / ssum;
        theta_scratch[i * KT + k] = t;
        theta_dout[i * KT + k] = t;
    }
    red[k] = (k < KT) ? kl : 0.f; __syncthreads();
    for (int s = 64; s > 0; s >>= 1) { if (k < s) red[k] += red[k + s]; __syncthreads(); }
    if (k == 0) atomicAdd(kl_acc, 0.5f * red[0]);
}

// ---------------- row sum of squares (one warp per row) ----------------
__global__ void rownorm2_kernel(const float* __restrict__ X, float* __restrict__ out, int R, int D) {
    int warp = (blockIdx.x * blockDim.x + threadIdx.x) >> 5;
    int lane = threadIdx.x & 31;
    if (warp >= R) return;
    float s = 0.f;
    for (int d = lane; d < D; d += 32) { float v = X[(size_t)warp * D + d]; s = fmaf(v, v, s); }
    for (int o = 16; o; o >>= 1) s += __shfl_down_sync(0xffffffffu, s, o);
    if (lane == 0) out[warp] = s;
}

__global__ void transpose_topic(const float* __restrict__ T, float* __restrict__ Tt) {
    int idx = blockIdx.x * blockDim.x + threadIdx.x;
    if (idx < KT * DE) { int k = idx / DE, d = idx % DE; Tt[d * KT + k] = T[idx]; }
}

// ---------------- beta: exp(-dist/tau) + column sums ----------------
__global__ void beta_pass1(const float* __restrict__ G, const float* __restrict__ wnorm,
                           const float* __restrict__ tnorm, float* __restrict__ beta_scr,
                           float* __restrict__ colsum, int V)
{
    __shared__ float tn_s[KT];
    __shared__ float wsum[8];
    int v = blockIdx.x * 256 + threadIdx.x;
    if (threadIdx.x < KT) tn_s[threadIdx.x] = tnorm[threadIdx.x];
    __syncthreads();
    bool ok = v < V;
    float wn = ok ? wnorm[v] : 0.f;
    int lane = threadIdx.x & 31, wid = threadIdx.x >> 5;
    for (int k = 0; k < KT; k++) {
        float e = 0.f;
        if (ok) {
            float sq = wn + tn_s[k] - 2.f * G[(size_t)v * KT + k];
            float d = sqrtf(fmaxf(sq, 0.f));
            e = expf(-d / TAU_);
            beta_scr[(size_t)k * V + v] = e;
        }
        float s = e;
        for (int o = 16; o; o >>= 1) s += __shfl_down_sync(0xffffffffu, s, o);
        if (lane == 0) wsum[wid] = s;
        __syncthreads();
        if (threadIdx.x == 0) {
            float t = 0.f;
            for (int w = 0; w < 8; w++) t += wsum[w];
            atomicAdd(&colsum[k], t);
        }
        __syncthreads();
    }
}

// normalize; write BOTH aligned scratch (for recon GEMM) and d_out (scalar stores)
__global__ void beta_pass2(float* __restrict__ beta_scr, float* __restrict__ beta_dout,
                           const float* __restrict__ colsum, int V) {
    int total = KT * V;
    for (int idx = blockIdx.x * blockDim.x + threadIdx.x; idx < total; idx += gridDim.x * blockDim.x) {
        int k = idx / V;
        float b = beta_scr[idx] / colsum[k];
        beta_scr[idx] = b;
        beta_dout[idx] = b;
    }
}

// ---------------- fused recon loss: online logsumexp + dot, one block per row ----------------
__global__ void recon_loss_kernel(const float* __restrict__ x, const float* __restrict__ recon,
                                  int V, float* acc)
{
    int i = blockIdx.x;
    int tid = threadIdx.x; // 256
    float m = -1e30f, s = 0.f, dot = 0.f, sx = 0.f;
    for (int v = tid; v < V; v += 256) {
        float r = recon[(size_t)i * V + v];
        float xv = x[(size_t)i * V + v];
        if (r > m) { s = s * expf(m - r) + 1.f; m = r; }
        else s += expf(r - m);
        dot = fmaf(xv, r, dot);
        sx += xv;
    }
    __shared__ float sm[256], ss[256], sd[256], sxs[256];
    sm[tid] = m; ss[tid] = s; sd[tid] = dot; sxs[tid] = sx;
    __syncthreads();
    for (int o = 128; o; o >>= 1) {
        if (tid < o) {
            float m1 = sm[tid], s1 = ss[tid];
            float m2 = sm[tid + o], s2 = ss[tid + o];
            float M_ = fmaxf(m1, m2);
            sm[tid] = M_;
            ss[tid] = s1 * expf(m1 - M_) + s2 * expf(m2 - M_);
            sd[tid] += sd[tid + o];
            sxs[tid] += sxs[tid + o];
        }
        __syncthreads();
    }
    if (tid == 0) {
        float lse = sm[0] + logf(ss[0]);
        atomicAdd(acc, -sd[0] + sxs[0] * lse);
    }
}

// ---------------- contrastive ----------------
__global__ void select_norm_kernel(const float* __restrict__ theta_en,
                                   const float* __restrict__ theta_cn, float* __restrict__ tn)
{
    int i = blockIdx.x;
    int k = threadIdx.x; // 128
    __shared__ float red[128];
    const float* src = ((i & 1) == 0) ? theta_en : theta_cn;
    float v = (k < KT) ? src[i * KT + k] : 0.f;
    red[k] = v * v; __syncthreads();
    for (int s = 64; s > 0; s >>= 1) { if (k < s) red[k] += red[k + s]; __syncthreads(); }
    float nrm = fmaxf(sqrtf(red[0]), 1e-8f);
    if (k < KT) tn[i * KT + k] = v / nrm;
}

__global__ void contrast_kernel(const float* __restrict__ tn, const int* __restrict__ cid, float* acc)
{
    int i = blockIdx.x;
    int tid = threadIdx.x; // 256
    __shared__ float ti[KT];
    if (tid < KT) ti[tid] = tn[i * KT + tid];
    __syncthreads();
    int ci = cid[i];
    bool vi = ci > 0;
    float pos = 0.f, neg = 0.f, pcnt = 0.f;
    for (int j = tid; j < B_SZ; j += 256) {
        if (j == i) continue;
        float s = 0.f;
        const float* tj = &tn[j * KT];
#pragma unroll 4
        for (int k = 0; k < KT; k++) s = fmaf(ti[k], tj[k], s);
        float E = expf(s / TAU_);
        neg += E;
        int cj = cid[j];
        if (vi && cj > 0 && cj == ci) { pos += E; pcnt += 1.f; }
    }
    __shared__ float r1[256], r2[256], r3[256];
    r1[tid] = pos; r2[tid] = neg; r3[tid] = pcnt;
    __syncthreads();
    for (int o = 128; o; o >>= 1) {
        if (tid < o) { r1[tid] += r1[tid + o]; r2[tid] += r2[tid + o]; r3[tid] += r3[tid + o]; }
        __syncthreads();
    }
    if (tid == 0) {
        if (vi && r3[0] > 0.5f) {
            float per = -logf(r1[0] / (r1[0] + r2[0] + 1e-8f));
            atomicAdd(&acc[4], per);
            atomicAdd(&acc[5], 1.f);
        }
    }
}

// ---------------- alignment (Sinkhorn) ----------------
__global__ void norm_topic_kernel(const float* __restrict__ T, float* __restrict__ Tn) {
    int k = blockIdx.x; // 100
    int d = threadIdx.x; // 128
    __shared__ float red[128];
    float s = 0.f;
    for (int dd = d; dd < DE; dd += 128) { float v = T[k * DE + dd]; s = fmaf(v, v, s); }
    red[d] = s; __syncthreads();
    for (int o = 64; o > 0; o >>= 1) { if (d < o) red[d] += red[d + o]; __syncthreads(); }
    float nrm = fmaxf(sqrtf(red[0]), 1e-8f);
    for (int dd = d; dd < DE; dd += 128) Tn[k * DE + dd] = T[k * DE + dd] / nrm;
}

__global__ void cmat_kernel(const float* __restrict__ Tn, float* __restrict__ C) {
    int i = blockIdx.x; // 100
    __shared__ float ti[DE];
    for (int d = threadIdx.x; d < DE; d += 128) ti[d] = Tn[i * DE + d];
    __syncthreads();
    for (int j = threadIdx.x; j < KT; j += 128) {
        float s = 0.f;
        for (int d = 0; d < DE; d++) s = fmaf(ti[d], Tn[j * DE + d], s);
        C[i * KT + j] = 1.f - s;
    }
}

__global__ void sinkhorn_kernel(const float* __restrict__ C, float* acc) {
    __shared__ float Ks[KT * KT];
    __shared__ float u[KT], v[KT];
    __shared__ float red[256];
    int tid = threadIdx.x; // 256
    for (int idx = tid; idx < KT * KT; idx += 256) Ks[idx] = expf(-C[idx] / EPS_SK);
    if (tid < KT) { u[tid] = 1.f; v[tid] = 1.f; }
    __syncthreads();
    const float a = 1.f / KT;
    for (int it = 0; it < 50; it++) {
        if (tid < KT) {
            float d = 1e-8f;
            for (int j = 0; j < KT; j++) d = fmaf(Ks[tid * KT + j], v[j], d);
            u[tid] = a / d;
        }
        __syncthreads();
        if (tid < KT) {
            float d = 1e-8f;
            for (int i2 = 0; i2 < KT; i2++) d = fmaf(Ks[i2 * KT + tid], u[i2], d);
            v[tid] = a / d;
        }
        __syncthreads();
    }
    float s = 0.f;
    for (int idx = tid; idx < KT * KT; idx += 256) {
        int i2 = idx / KT, j = idx % KT;
        s += u[i2] * Ks[idx] * v[j] * C[idx];
    }
    red[tid] = s; __syncthreads();
    for (int o = 128; o; o >>= 1) { if (tid < o) red[tid] += red[tid + o]; __syncthreads(); }
    if (tid == 0) acc[6] = red[0];
}

__global__ void finalize_kernel(const float* __restrict__ acc, float* __restrict__ out) {
    float tm_en = acc[0] / (float)B_SZ + acc[1] / (float)B_SZ;
    float tm_cn = acc[2] / (float)B_SZ + acc[3] / (float)B_SZ;
    float contrast = acc[4] / (acc[5] + 1e-8f);
    float align = acc[6];
    out[0] = tm_en + tm_cn + contrast + align;
    out[1] = tm_en;
    out[2] = tm_cn;
    out[3] = contrast;
    out[4] = align;
}

// ---------------- host ----------------
static inline void launch_gemm(const float* A, const float* B, float* C,
                               int M, int N, int K, int gz, int mode)
{
    int ksteps = (K + 15) / 16;
    int per = (ksteps + gz - 1) / gz;
    dim3 grid((N + 127) / 128, (M + 127) / 128, gz);
    gemm128<<<grid, 256>>>(A, B, C, M, N, K, per, mode);
}

extern "C" void kernel_launch(void* const* d_in, const int* in_sizes, int n_in,
                              void* d_out, int out_size)
{
    const float* x_en   = (const float*)d_in[0];
    const float* x_cn   = (const float*)d_in[1];
    const int*   cid    = (const int*)  d_in[2];
    const float* eps_en = (const float*)d_in[3];
    const float* eps_cn = (const float*)d_in[4];
    const float* W1_en  = (const float*)d_in[5];
    const float* b1_en  = (const float*)d_in[6];
    const float* W2_en  = (const float*)d_in[7];
    const float* b2_en  = (const float*)d_in[8];
    const float* Wmu_en = (const float*)d_in[9];
    const float* bmu_en = (const float*)d_in[10];
    const float* Wlv_en = (const float*)d_in[11];
    const float* blv_en = (const float*)d_in[12];
    const float* W1_cn  = (const float*)d_in[13];
    const float* b1_cn  = (const float*)d_in[14];
    const float* W2_cn  = (const float*)d_in[15];
    const float* b2_cn  = (const float*)d_in[16];
    const float* Wmu_cn = (const float*)d_in[17];
    const float* bmu_cn = (const float*)d_in[18];
    const float* Wlv_cn = (const float*)d_in[19];
    const float* blv_cn = (const float*)d_in[20];
    const float* we_en  = (const float*)d_in[21];
    const float* we_cn  = (const float*)d_in[22];
    const float* topic  = (const float*)d_in[23];

    float* out = (float*)d_out;
    float* theta_en_out = out + 5;
    float* theta_cn_out = theta_en_out + B_SZ * KT;
    float* beta_en_out  = theta_cn_out + B_SZ * KT;
    float* beta_cn_out  = beta_en_out + KT * NV_EN;

    float *h1, *h2, *mu, *lv, *G, *beta, *recon, *th_en, *th_cn,
          *wn, *tnm, *tT, *tnb, *tnT, *Cm, *cs, *acc;
    cudaGetSymbolAddress((void**)&h1,    g_h1);
    cudaGetSymbolAddress((void**)&h2,    g_h2);
    cudaGetSymbolAddress((void**)&mu,    g_mu);
    cudaGetSymbolAddress((void**)&lv,    g_lv);
    cudaGetSymbolAddress((void**)&G,     g_G);
    cudaGetSymbolAddress((void**)&beta,  g_beta);
    cudaGetSymbolAddress((void**)&recon, g_recon);
    cudaGetSymbolAddress((void**)&th_en, g_theta_en);
    cudaGetSymbolAddress((void**)&th_cn, g_theta_cn);
    cudaGetSymbolAddress((void**)&wn,    g_wnorm);
    cudaGetSymbolAddress((void**)&tnm,   g_tnorm);
    cudaGetSymbolAddress((void**)&tT,    g_topicT);
    cudaGetSymbolAddress((void**)&tnb,   g_tn);
    cudaGetSymbolAddress((void**)&tnT,   g_tnT);
    cudaGetSymbolAddress((void**)&Cm,    g_C);
    cudaGetSymbolAddress((void**)&cs,    g_colsum);
    cudaGetSymbolAddress((void**)&acc,   g_acc);

    zero_kernel<<<1, 64>>>(acc, 8);

    // ===== EN encoder =====
    zero_kernel<<<1024, 256>>>(h1, B_SZ * HD);
    launch_gemm(x_en, W1_en, h1, B_SZ, HD, NV_EN, 20, 1);
    bias_softplus<<<1024, 256>>>(h1, b1_en, B_SZ, HD);
    zero_kernel<<<1024, 256>>>(h2, B_SZ * HD);
    launch_gemm(h1, W2_en, h2, B_SZ, HD, HD, 8, 1);
    bias_softplus<<<1024, 256>>>(h2, b2_en, B_SZ, HD);
    zero_kernel<<<256, 256>>>(mu, B_SZ * KT);
    zero_kernel<<<256, 256>>>(lv, B_SZ * KT);
    launch_gemm(h2, Wmu_en, mu, B_SZ, KT, HD, 16, 1);
    launch_gemm(h2, Wlv_en, lv, B_SZ, KT, HD, 16, 1);
    theta_kl_kernel<<<B_SZ, 128>>>(mu, lv, bmu_en, blv_en, eps_en, th_en, theta_en_out, acc + 1);

    // ===== CN encoder =====
    zero_kernel<<<1024, 256>>>(h1, B_SZ * HD);
    launch_gemm(x_cn, W1_cn, h1, B_SZ, HD, NV_CN, 20, 1);
    bias_softplus<<<1024, 256>>>(h1, b1_cn, B_SZ, HD);
    zero_kernel<<<1024, 256>>>(h2, B_SZ * HD);
    launch_gemm(h1, W2_cn, h2, B_SZ, HD, HD, 8, 1);
    bias_softplus<<<1024, 256>>>(h2, b2_cn, B_SZ, HD);
    zero_kernel<<<256, 256>>>(mu, B_SZ * KT);
    zero_kernel<<<256, 256>>>(lv, B_SZ * KT);
    launch_gemm(h2, Wmu_cn, mu, B_SZ, KT, HD, 16, 1);
    launch_gemm(h2, Wlv_cn, lv, B_SZ, KT, HD, 16, 1);
    theta_kl_kernel<<<B_SZ, 128>>>(mu, lv, bmu_cn, blv_cn, eps_cn, th_cn, theta_cn_out, acc + 3);

    // ===== beta (shared pieces) =====
    transpose_topic<<<(KT * DE + 255) / 256, 256>>>(topic, tT);
    rownorm2_kernel<<<(KT * 32 + 255) / 256, 256>>>(topic, tnm, KT, DE);

    // ===== beta EN + recon EN =====
    rownorm2_kernel<<<(NV_EN * 32 + 255) / 256, 256>>>(we_en, wn, NV_EN, DE);
    launch_gemm(we_en, tT, G, NV_EN, KT, DE, 1, 0);
    zero_kernel<<<1, 128>>>(cs, KT);
    beta_pass1<<<(NV_EN + 255) / 256, 256>>>(G, wn, tnm, beta, cs, NV_EN);
    beta_pass2<<<2048, 256>>>(beta, beta_en_out, cs, NV_EN);
    launch_gemm(th_en, beta, recon, B_SZ, NV_EN, KT, 1, 0);
    recon_loss_kernel<<<B_SZ, 256>>>(x_en, recon, NV_EN, acc + 0);

    // ===== beta CN + recon CN =====
    rownorm2_kernel<<<(NV_CN * 32 + 255) / 256, 256>>>(we_cn, wn, NV_CN, DE);
    launch_gemm(we_cn, tT, G, NV_CN, KT, DE, 1, 0);
    zero_kernel<<<1, 128>>>(cs, KT);
    beta_pass1<<<(NV_CN + 255) / 256, 256>>>(G, wn, tnm, beta, cs, NV_CN);
    beta_pass2<<<2048, 256>>>(beta, beta_cn_out, cs, NV_CN);
    launch_gemm(th_cn, beta, recon, B_SZ, NV_CN, KT, 1, 0);
    recon_loss_kernel<<<B_SZ, 256>>>(x_cn, recon, NV_CN, acc + 2);

    // ===== contrastive =====
    select_norm_kernel<<<B_SZ, 128>>>(th_en, th_cn, tnb);
    contrast_kernel<<<B_SZ, 256>>>(tnb, cid, acc);

    // ===== alignment =====
    norm_topic_kernel<<<KT, 128>>>(topic, tnT);
    cmat_kernel<<<KT, 128>>>(tnT, Cm);
    sinkhorn_kernel<<<1, 256>>>(Cm, acc);

    finalize_kernel<<<1, 1>>>(acc, out);
}

// round 6
// speedup vs baseline: 1.5797x; 1.5797x over previous
#include <cuda_runtime.h>
#include <cuda_bf16.h>
#include <math.h>
#include <stdint.h>

#define B_SZ 512
#define NV_EN 30000
#define NV_CN 20000
#define KT 100
#define HD 512
#define DE 300
#define TAU_ 1.0f
#define EPS_SK 0.1f

typedef __nv_bfloat16 bf16;

// ---------------- device scratch (static, no allocations, aligned) ----------------
#define BIGKP 30016  // ceil(30000/64)*64
__device__ __align__(16) bf16 g_Ahi[B_SZ * BIGKP];
__device__ __align__(16) bf16 g_Alo[B_SZ * BIGKP];
__device__ __align__(16) bf16 g_Bhi[B_SZ * BIGKP];
__device__ __align__(16) bf16 g_Blo[B_SZ * BIGKP];
__device__ __align__(16) float g_h1[B_SZ * HD];
__device__ __align__(16) float g_h2[B_SZ * HD];
__device__ __align__(16) float g_mulv[B_SZ * 200];
__device__ __align__(16) float g_G[NV_EN * KT];
__device__ __align__(16) float g_beta[KT * NV_EN];
__device__ __align__(16) float g_recon[B_SZ * NV_EN];
__device__ __align__(16) float g_theta_en[B_SZ * KT];
__device__ __align__(16) float g_theta_cn[B_SZ * KT];
__device__ __align__(16) float g_wnorm[NV_EN];
__device__ __align__(16) float g_tnorm[KT];
__device__ __align__(16) float g_tn[B_SZ * KT];
__device__ __align__(16) float g_tnT[KT * DE];
__device__ __align__(16) float g_C[KT * KT];
__device__ __align__(16) float g_colsum[KT];
__device__ __align__(16) float g_acc[8];

// ================= split-bf16 mma.sync GEMM: C = A[MxKp] @ B'[NxKp]^T =================
// A,B given as hi/lo bf16 pairs, row-major, padded K stride Kp (Kp % 32 == 0, pad zeroed).
// Block tile 128x128, Kc=32 per chunk. 8 warps (4Mx2N), warp tile 32x64,
// m16n8k16 fragments loaded with direct LDS.32 (row stride 40 bf16 -> conflict-free).
// mode 0: store (REQUIRES grid.z covering all K, i.e. z=1), 1: atomicAdd (split-K).
#define KC 32
#define AST 40   // smem row stride in bf16

__device__ __forceinline__ void mma16816(float* c, const uint32_t* a, uint32_t b0, uint32_t b1) {
    asm volatile(
        "mma.sync.aligned.m16n8k16.row.col.f32.bf16.bf16.f32 "
        "{%0,%1,%2,%3}, {%4,%5,%6,%7}, {%8,%9}, {%0,%1,%2,%3};"
        : "+f"(c[0]), "+f"(c[1]), "+f"(c[2]), "+f"(c[3])
        : "r"(a[0]), "r"(a[1]), "r"(a[2]), "r"(a[3]), "r"(b0), "r"(b1));
}

__global__ __launch_bounds__(256)
void tc_gemm(const bf16* __restrict__ Ahi, const bf16* __restrict__ Alo,
             const bf16* __restrict__ Bhi, const bf16* __restrict__ Blo,
             float* __restrict__ C, int M, int N, int Kp,
             int chunksPerZ, int mode)
{
    __shared__ __align__(16) bf16 sA[2][128 * AST];
    __shared__ __align__(16) bf16 sB[2][128 * AST];

    int tid = threadIdx.x;
    int warp = tid >> 5, lane = tid & 31;
    int wm = warp >> 1, wn = warp & 1;          // 4 x 2 warp grid
    int row0 = blockIdx.y * 128;
    int col0 = blockIdx.x * 128;
    int totalChunks = Kp / KC;
    int c0 = blockIdx.z * chunksPerZ;
    int nC = min(chunksPerZ, totalChunks - c0);
    if (nC <= 0) return;

    float acc[2][8][4];
#pragma unroll
    for (int i = 0; i < 2; i++)
#pragma unroll
        for (int j = 0; j < 8; j++)
#pragma unroll
            for (int q = 0; q < 4; q++) acc[i][j][q] = 0.f;

    int g = lane >> 2, t4 = lane & 3;

    for (int lc = 0; lc < nC; lc++) {
        int k0 = (c0 + lc) * KC;
        // ---- load 4 tiles (128 rows x 32 bf16 each; 512 uint4 per tile) ----
#pragma unroll
        for (int it = 0; it < 8; it++) {
            int lin = tid + it * 256;          // 0..2047
            int tile = lin >> 9;               // 0:Ah 1:Al 2:Bh 3:Bl
            int rem = lin & 511;
            int r = rem >> 2;
            int j = rem & 3;
            const bf16* src = (tile == 0) ? Ahi : (tile == 1) ? Alo : (tile == 2) ? Bhi : Blo;
            bf16* dst = (tile == 0) ? sA[0] : (tile == 1) ? sA[1] : (tile == 2) ? sB[0] : sB[1];
            int gr = ((tile < 2) ? row0 : col0) + r;
            int lim = (tile < 2) ? M : N;
            uint4 v = make_uint4(0u, 0u, 0u, 0u);
            if (gr < lim)
                v = *reinterpret_cast<const uint4*>(src + (size_t)gr * Kp + k0 + j * 8);
            *reinterpret_cast<uint4*>(dst + r * AST + j * 8) = v;
        }
        __syncthreads();

#pragma unroll
        for (int ks = 0; ks < 2; ks++) {
            int kb = ks * 16 + t4 * 2;
            uint32_t ah[2][4], al[2][4];
#pragma unroll
            for (int mf = 0; mf < 2; mf++) {
                int ar = wm * 32 + mf * 16 + g;
                int base = ar * AST + kb;
                ah[mf][0] = *reinterpret_cast<const uint32_t*>(&sA[0][base]);
                ah[mf][1] = *reinterpret_cast<const uint32_t*>(&sA[0][base + 8 * AST]);
                ah[mf][2] = *reinterpret_cast<const uint32_t*>(&sA[0][base + 8]);
                ah[mf][3] = *reinterpret_cast<const uint32_t*>(&sA[0][base + 8 * AST + 8]);
                al[mf][0] = *reinterpret_cast<const uint32_t*>(&sA[1][base]);
                al[mf][1] = *reinterpret_cast<const uint32_t*>(&sA[1][base + 8 * AST]);
                al[mf][2] = *reinterpret_cast<const uint32_t*>(&sA[1][base + 8]);
                al[mf][3] = *reinterpret_cast<const uint32_t*>(&sA[1][base + 8 * AST + 8]);
            }
#pragma unroll
            for (int nf = 0; nf < 8; nf++) {
                int bn = wn * 64 + nf * 8 + g;
                int bbase = bn * AST + kb;
                uint32_t bh0 = *reinterpret_cast<const uint32_t*>(&sB[0][bbase]);
                uint32_t bh1 = *reinterpret_cast<const uint32_t*>(&sB[0][bbase + 8]);
                uint32_t bl0 = *reinterpret_cast<const uint32_t*>(&sB[1][bbase]);
                uint32_t bl1 = *reinterpret_cast<const uint32_t*>(&sB[1][bbase + 8]);
#pragma unroll
                for (int mf = 0; mf < 2; mf++) {
                    mma16816(acc[mf][nf], ah[mf], bh0, bh1);
                    mma16816(acc[mf][nf], ah[mf], bl0, bl1);
                    mma16816(acc[mf][nf], al[mf], bh0, bh1);
                }
            }
        }
        __syncthreads();
    }

    // ---- epilogue ----
#pragma unroll
    for (int mf = 0; mf < 2; mf++) {
#pragma unroll
        for (int nf = 0; nf < 8; nf++) {
            int r = row0 + wm * 32 + mf * 16 + g;
            int c = col0 + wn * 64 + nf * 8 + t4 * 2;
            float* a4 = acc[mf][nf];
#pragma unroll
            for (int h = 0; h < 2; h++) {   // h: row +0 / +8
                int rr = r + h * 8;
                if (rr >= M) continue;
#pragma unroll
                for (int q = 0; q < 2; q++) {
                    int cc = c + q;
                    if (cc >= N) continue;
                    float v = a4[h * 2 + q];
                    if (mode) atomicAdd(&C[(size_t)rr * N + cc], v);
                    else C[(size_t)rr * N + cc] = v;
                }
            }
        }
    }
}

// ---------------- split conversion: src fp32 [R x K] -> hi/lo bf16 [R x Kp] ----------------
__device__ __forceinline__ void split2(float x, bf16& h, bf16& l) {
    h = __float2bfloat16(x);
    l = __float2bfloat16(x - __bfloat162float(h));
}

__global__ void conv_pad(const float* __restrict__ src, bf16* __restrict__ hi, bf16* __restrict__ lo,
                         int R, int K, int Kp) {
    size_t total = (size_t)R * Kp;
    for (size_t idx = blockIdx.x * (size_t)blockDim.x + threadIdx.x; idx < total;
         idx += (size_t)gridDim.x * blockDim.x) {
        int r = (int)(idx / Kp), k = (int)(idx % Kp);
        float v = (k < K) ? src[(size_t)r * K + k] : 0.f;
        bf16 h, l; split2(v, h, l);
        hi[idx] = h; lo[idx] = l;
    }
}

// transpose-convert: src fp32 [R(Kdim) x C(Ndim)] -> hi/lo bf16 [C x Kp], out[n*Kp+k] = src[k*C+n]
__global__ void tconv(const float* __restrict__ src, bf16* __restrict__ hi, bf16* __restrict__ lo,
                      int R, int C, int Kp) {
    __shared__ float t[32][33];
    int kb = blockIdx.y * 32, nb = blockIdx.x * 32;
    int tx = threadIdx.x, ty = threadIdx.y;  // 32 x 8
#pragma unroll
    for (int i = 0; i < 4; i++) {
        int r = kb + ty + i * 8, c = nb + tx;
        t[ty + i * 8][tx] = (r < R && c < C) ? src[(size_t)r * C + c] : 0.f;
    }
    __syncthreads();
#pragma unroll
    for (int i = 0; i < 4; i++) {
        int n = nb + ty + i * 8, k = kb + tx;
        if (n < C && k < Kp) {
            bf16 h, l; split2(t[tx][ty + i * 8], h, l);
            hi[(size_t)n * Kp + k] = h;
            lo[(size_t)n * Kp + k] = l;
        }
    }
}

// ---------------- elementwise / reductions ----------------
__global__ void zero_kernel(float* p, int n) {
    for (int i = blockIdx.x * blockDim.x + threadIdx.x; i < n; i += gridDim.x * blockDim.x)
        p[i] = 0.f;
}

__global__ void bias_softplus(float* X, const float* __restrict__ bias, int M, int N) {
    int total = M * N;
    for (int idx = blockIdx.x * blockDim.x + threadIdx.x; idx < total; idx += gridDim.x * blockDim.x) {
        int j = idx % N;
        float v = X[idx] + bias[j];
        X[idx] = fmaxf(v, 0.f) + log1pf(expf(-fabsf(v)));
    }
}

// mu/lv packed in mulv [B x 200]: mu cols 0-99, lv cols 100-199
__global__ void theta_kl_kernel(const float* __restrict__ mulv,
                                const float* __restrict__ bmu, const float* __restrict__ blv,
                                const float* __restrict__ eps, float* __restrict__ theta_scratch,
                                float* __restrict__ theta_dout, float* kl_acc)
{
    int i = blockIdx.x;
    int k = threadIdx.x; // 128
    __shared__ float red[128];
    float zv = -1e30f, kl = 0.f;
    if (k < KT) {
        float mu = mulv[i * 200 + k] + bmu[k];
        float lv = mulv[i * 200 + 100 + k] + blv[k];
        zv = mu + eps[i * KT + k] * expf(0.5f * lv);
        kl = expf(lv) + mu * mu - 1.f - lv;
    }
    red[k] = zv; __syncthreads();
    for (int s = 64; s > 0; s >>= 1) { if (k < s) red[k] = fmaxf(red[k], red[k + s]); __syncthreads(); }
    float m = red[0]; __syncthreads();
    float e = (k < KT) ? expf(zv - m) : 0.f;
    red[k] = e; __syncthreads();
    for (int s = 64; s > 0; s >>= 1) { if (k < s) red[k] += red[k + s]; __syncthreads(); }
    float ssum = red[0]; __syncthreads();
    if (k < KT) {
        float t = e / ssum;
        theta_scratch[i * KT + k] = t;
        theta_dout[i * KT + k] = t;
    }
    red[k] = (k < KT) ? kl : 0.f; __syncthreads();
    for (int s = 64; s > 0; s >>= 1) { if (k < s) red[k] += red[k + s]; __syncthreads(); }
    if (k == 0) atomicAdd(kl_acc, 0.5f * red[0]);
}

__global__ void rownorm2_kernel(const float* __restrict__ X, float* __restrict__ out, int R, int D) {
    int warp = (blockIdx.x * blockDim.x + threadIdx.x) >> 5;
    int lane = threadIdx.x & 31;
    if (warp >= R) return;
    float s = 0.f;
    for (int d = lane; d < D; d += 32) { float v = X[(size_t)warp * D + d]; s = fmaf(v, v, s); }
    for (int o = 16; o; o >>= 1) s += __shfl_down_sync(0xffffffffu, s, o);
    if (lane == 0) out[warp] = s;
}

__global__ void beta_pass1(const float* __restrict__ G, const float* __restrict__ wnorm,
                           const float* __restrict__ tnorm, float* __restrict__ beta_scr,
                           float* __restrict__ colsum, int V)
{
    __shared__ float tn_s[KT];
    __shared__ float wsum[8];
    int v = blockIdx.x * 256 + threadIdx.x;
    if (threadIdx.x < KT) tn_s[threadIdx.x] = tnorm[threadIdx.x];
    __syncthreads();
    bool ok = v < V;
    float wn = ok ? wnorm[v] : 0.f;
    int lane = threadIdx.x & 31, wid = threadIdx.x >> 5;
    for (int k = 0; k < KT; k++) {
        float e = 0.f;
        if (ok) {
            float sq = wn + tn_s[k] - 2.f * G[(size_t)v * KT + k];
            float d = sqrtf(fmaxf(sq, 0.f));
            e = expf(-d / TAU_);
            beta_scr[(size_t)k * V + v] = e;
        }
        float s = e;
        for (int o = 16; o; o >>= 1) s += __shfl_down_sync(0xffffffffu, s, o);
        if (lane == 0) wsum[wid] = s;
        __syncthreads();
        if (threadIdx.x == 0) {
            float t = 0.f;
            for (int w = 0; w < 8; w++) t += wsum[w];
            atomicAdd(&colsum[k], t);
        }
        __syncthreads();
    }
}

__global__ void beta_pass2(float* __restrict__ beta_scr, float* __restrict__ beta_dout,
                           const float* __restrict__ colsum, int V) {
    int total = KT * V;
    for (int idx = blockIdx.x * blockDim.x + threadIdx.x; idx < total; idx += gridDim.x * blockDim.x) {
        int k = idx / V;
        float b = beta_scr[idx] / colsum[k];
        beta_scr[idx] = b;
        beta_dout[idx] = b;
    }
}

__global__ void recon_loss_kernel(const float* __restrict__ x, const float* __restrict__ recon,
                                  int V, float* acc)
{
    int i = blockIdx.x;
    int tid = threadIdx.x; // 256
    float m = -1e30f, s = 0.f, dot = 0.f, sx = 0.f;
    for (int v = tid; v < V; v += 256) {
        float r = recon[(size_t)i * V + v];
        float xv = x[(size_t)i * V + v];
        if (r > m) { s = s * expf(m - r) + 1.f; m = r; }
        else s += expf(r - m);
        dot = fmaf(xv, r, dot);
        sx += xv;
    }
    __shared__ float sm[256], ss[256], sd[256], sxs[256];
    sm[tid] = m; ss[tid] = s; sd[tid] = dot; sxs[tid] = sx;
    __syncthreads();
    for (int o = 128; o; o >>= 1) {
        if (tid < o) {
            float m1 = sm[tid], s1 = ss[tid];
            float m2 = sm[tid + o], s2 = ss[tid + o];
            float M_ = fmaxf(m1, m2);
            sm[tid] = M_;
            ss[tid] = s1 * expf(m1 - M_) + s2 * expf(m2 - M_);
            sd[tid] += sd[tid + o];
            sxs[tid] += sxs[tid + o];
        }
        __syncthreads();
    }
    if (tid == 0) {
        float lse = sm[0] + logf(ss[0]);
        atomicAdd(acc, -sd[0] + sxs[0] * lse);
    }
}

__global__ void select_norm_kernel(const float* __restrict__ theta_en,
                                   const float* __restrict__ theta_cn, float* __restrict__ tn)
{
    int i = blockIdx.x;
    int k = threadIdx.x; // 128
    __shared__ float red[128];
    const float* src = ((i & 1) == 0) ? theta_en : theta_cn;
    float v = (k < KT) ? src[i * KT + k] : 0.f;
    red[k] = v * v; __syncthreads();
    for (int s = 64; s > 0; s >>= 1) { if (k < s) red[k] += red[k + s]; __syncthreads(); }
    float nrm = fmaxf(sqrtf(red[0]), 1e-8f);
    if (k < KT) tn[i * KT + k] = v / nrm;
}

__global__ void contrast_kernel(const float* __restrict__ tn, const int* __restrict__ cid, float* acc)
{
    int i = blockIdx.x;
    int tid = threadIdx.x; // 256
    __shared__ float ti[KT];
    if (tid < KT) ti[tid] = tn[i * KT + tid];
    __syncthreads();
    int ci = cid[i];
    bool vi = ci > 0;
    float pos = 0.f, neg = 0.f, pcnt = 0.f;
    for (int j = tid; j < B_SZ; j += 256) {
        if (j == i) continue;
        float s = 0.f;
        const float* tj = &tn[j * KT];
#pragma unroll 4
        for (int k = 0; k < KT; k++) s = fmaf(ti[k], tj[k], s);
        float E = expf(s / TAU_);
        neg += E;
        int cj = cid[j];
        if (vi && cj > 0 && cj == ci) { pos += E; pcnt += 1.f; }
    }
    __shared__ float r1[256], r2[256], r3[256];
    r1[tid] = pos; r2[tid] = neg; r3[tid] = pcnt;
    __syncthreads();
    for (int o = 128; o; o >>= 1) {
        if (tid < o) { r1[tid] += r1[tid + o]; r2[tid] += r2[tid + o]; r3[tid] += r3[tid + o]; }
        __syncthreads();
    }
    if (tid == 0) {
        if (vi && r3[0] > 0.5f) {
            float per = -logf(r1[0] / (r1[0] + r2[0] + 1e-8f));
            atomicAdd(&acc[4], per);
            atomicAdd(&acc[5], 1.f);
        }
    }
}

__global__ void norm_topic_kernel(const float* __restrict__ T, float* __restrict__ Tn) {
    int k = blockIdx.x; // 100
    int d = threadIdx.x; // 128
    __shared__ float red[128];
    float s = 0.f;
    for (int dd = d; dd < DE; dd += 128) { float v = T[k * DE + dd]; s = fmaf(v, v, s); }
    red[d] = s; __syncthreads();
    for (int o = 64; o > 0; o >>= 1) { if (d < o) red[d] += red[d + o]; __syncthreads(); }
    float nrm = fmaxf(sqrtf(red[0]), 1e-8f);
    for (int dd = d; dd < DE; dd += 128) Tn[k * DE + dd] = T[k * DE + dd] / nrm;
}

__global__ void cmat_kernel(const float* __restrict__ Tn, float* __restrict__ C) {
    int i = blockIdx.x; // 100
    __shared__ float ti[DE];
    for (int d = threadIdx.x; d < DE; d += 128) ti[d] = Tn[i * DE + d];
    __syncthreads();
    for (int j = threadIdx.x; j < KT; j += 128) {
        float s = 0.f;
        for (int d = 0; d < DE; d++) s = fmaf(ti[d], Tn[j * DE + d], s);
        C[i * KT + j] = 1.f - s;
    }
}

__global__ void sinkhorn_kernel(const float* __restrict__ C, float* acc) {
    __shared__ float Ks[KT * KT];
    __shared__ float u[KT], v[KT];
    __shared__ float red[256];
    int tid = threadIdx.x; // 256
    for (int idx = tid; idx < KT * KT; idx += 256) Ks[idx] = expf(-C[idx] / EPS_SK);
    if (tid < KT) { u[tid] = 1.f; v[tid] = 1.f; }
    __syncthreads();
    const float a = 1.f / KT;
    for (int it = 0; it < 50; it++) {
        if (tid < KT) {
            float d = 1e-8f;
            for (int j = 0; j < KT; j++) d = fmaf(Ks[tid * KT + j], v[j], d);
            u[tid] = a / d;
        }
        __syncthreads();
        if (tid < KT) {
            float d = 1e-8f;
            for (int i2 = 0; i2 < KT; i2++) d = fmaf(Ks[i2 * KT + tid], u[i2], d);
            v[tid] = a / d;
        }
        __syncthreads();
    }
    float s = 0.f;
    for (int idx = tid; idx < KT * KT; idx += 256) {
        int i2 = idx / KT, j = idx % KT;
        s += u[i2] * Ks[idx] * v[j] * C[idx];
    }
    red[tid] = s; __syncthreads();
    for (int o = 128; o; o >>= 1) { if (tid < o) red[tid] += red[tid + o]; __syncthreads(); }
    if (tid == 0) acc[6] = red[0];
}

__global__ void finalize_kernel(const float* __restrict__ acc, float* __restrict__ out) {
    float tm_en = acc[0] / (float)B_SZ + acc[1] / (float)B_SZ;
    float tm_cn = acc[2] / (float)B_SZ + acc[3] / (float)B_SZ;
    float contrast = acc[4] / (acc[5] + 1e-8f);
    float align = acc[6];
    out[0] = tm_en + tm_cn + contrast + align;
    out[1] = tm_en;
    out[2] = tm_cn;
    out[3] = contrast;
    out[4] = align;
}

// ---------------- host ----------------
static inline void launch_tc(const bf16* Ah, const bf16* Al, const bf16* Bh, const bf16* Bl,
                             float* C, int M, int N, int Kp, int z, int mode)
{
    int total = Kp / KC;
    int per = (total + z - 1) / z;
    dim3 g((N + 127) / 128, (M + 127) / 128, z);
    tc_gemm<<<g, 256>>>(Ah, Al, Bh, Bl, C, M, N, Kp, per, mode);
}

extern "C" void kernel_launch(void* const* d_in, const int* in_sizes, int n_in,
                              void* d_out, int out_size)
{
    const float* x_en   = (const float*)d_in[0];
    const float* x_cn   = (const float*)d_in[1];
    const int*   cid    = (const int*)  d_in[2];
    const float* eps_en = (const float*)d_in[3];
    const float* eps_cn = (const float*)d_in[4];
    const float* W1_en  = (const float*)d_in[5];
    const float* b1_en  = (const float*)d_in[6];
    const float* W2_en  = (const float*)d_in[7];
    const float* b2_en  = (const float*)d_in[8];
    const float* Wmu_en = (const float*)d_in[9];
    const float* bmu_en = (const float*)d_in[10];
    const float* Wlv_en = (const float*)d_in[11];
    const float* blv_en = (const float*)d_in[12];
    const float* W1_cn  = (const float*)d_in[13];
    const float* b1_cn  = (const float*)d_in[14];
    const float* W2_cn  = (const float*)d_in[15];
    const float* b2_cn  = (const float*)d_in[16];
    const float* Wmu_cn = (const float*)d_in[17];
    const float* bmu_cn = (const float*)d_in[18];
    const float* Wlv_cn = (const float*)d_in[19];
    const float* blv_cn = (const float*)d_in[20];
    const float* we_en  = (const float*)d_in[21];
    const float* we_cn  = (const float*)d_in[22];
    const float* topic  = (const float*)d_in[23];

    float* out = (float*)d_out;
    float* theta_en_out = out + 5;
    float* theta_cn_out = theta_en_out + B_SZ * KT;
    float* beta_en_out  = theta_cn_out + B_SZ * KT;
    float* beta_cn_out  = beta_en_out + KT * NV_EN;

    float *h1, *h2, *mulv, *G, *beta, *recon, *th_en, *th_cn,
          *wn, *tnm, *tnb, *tnT, *Cm, *cs, *acc;
    bf16 *Ahi, *Alo, *Bhi, *Blo;
    cudaGetSymbolAddress((void**)&Ahi,   g_Ahi);
    cudaGetSymbolAddress((void**)&Alo,   g_Alo);
    cudaGetSymbolAddress((void**)&Bhi,   g_Bhi);
    cudaGetSymbolAddress((void**)&Blo,   g_Blo);
    cudaGetSymbolAddress((void**)&h1,    g_h1);
    cudaGetSymbolAddress((void**)&h2,    g_h2);
    cudaGetSymbolAddress((void**)&mulv,  g_mulv);
    cudaGetSymbolAddress((void**)&G,     g_G);
    cudaGetSymbolAddress((void**)&beta,  g_beta);
    cudaGetSymbolAddress((void**)&recon, g_recon);
    cudaGetSymbolAddress((void**)&th_en, g_theta_en);
    cudaGetSymbolAddress((void**)&th_cn, g_theta_cn);
    cudaGetSymbolAddress((void**)&wn,    g_wnorm);
    cudaGetSymbolAddress((void**)&tnm,   g_tnorm);
    cudaGetSymbolAddress((void**)&tnb,   g_tn);
    cudaGetSymbolAddress((void**)&tnT,   g_tnT);
    cudaGetSymbolAddress((void**)&Cm,    g_C);
    cudaGetSymbolAddress((void**)&cs,    g_colsum);
    cudaGetSymbolAddress((void**)&acc,   g_acc);

    zero_kernel<<<1, 64>>>(acc, 8);

    dim3 tb(32, 8);

    // ================= EN encoder =================
    conv_pad<<<4096, 256>>>(x_en, Ahi, Alo, B_SZ, NV_EN, 30016);
    tconv<<<dim3(16, 938), tb>>>(W1_en, Bhi, Blo, NV_EN, HD, 30016);
    zero_kernel<<<1024, 256>>>(h1, B_SZ * HD);
    launch_tc(Ahi, Alo, Bhi, Blo, h1, B_SZ, HD, 30016, 16, 1);
    bias_softplus<<<1024, 256>>>(h1, b1_en, B_SZ, HD);

    conv_pad<<<1024, 256>>>(h1, Ahi, Alo, B_SZ, HD, 512);
    tconv<<<dim3(16, 16), tb>>>(W2_en, Bhi, Blo, HD, HD, 512);
    zero_kernel<<<1024, 256>>>(h2, B_SZ * HD);
    launch_tc(Ahi, Alo, Bhi, Blo, h2, B_SZ, HD, 512, 4, 1);
    bias_softplus<<<1024, 256>>>(h2, b2_en, B_SZ, HD);

    conv_pad<<<1024, 256>>>(h2, Ahi, Alo, B_SZ, HD, 512);
    tconv<<<dim3(4, 16), tb>>>(Wmu_en, Bhi, Blo, HD, KT, 512);
    tconv<<<dim3(4, 16), tb>>>(Wlv_en, Bhi + 100 * 512, Blo + 100 * 512, HD, KT, 512);
    zero_kernel<<<512, 256>>>(mulv, B_SZ * 200);
    launch_tc(Ahi, Alo, Bhi, Blo, mulv, B_SZ, 200, 512, 2, 1);
    theta_kl_kernel<<<B_SZ, 128>>>(mulv, bmu_en, blv_en, eps_en, th_en, theta_en_out, acc + 1);

    // ================= CN encoder =================
    conv_pad<<<4096, 256>>>(x_cn, Ahi, Alo, B_SZ, NV_CN, 20032);
    tconv<<<dim3(16, 626), tb>>>(W1_cn, Bhi, Blo, NV_CN, HD, 20032);
    zero_kernel<<<1024, 256>>>(h1, B_SZ * HD);
    launch_tc(Ahi, Alo, Bhi, Blo, h1, B_SZ, HD, 20032, 16, 1);
    bias_softplus<<<1024, 256>>>(h1, b1_cn, B_SZ, HD);

    conv_pad<<<1024, 256>>>(h1, Ahi, Alo, B_SZ, HD, 512);
    tconv<<<dim3(16, 16), tb>>>(W2_cn, Bhi, Blo, HD, HD, 512);
    zero_kernel<<<1024, 256>>>(h2, B_SZ * HD);
    launch_tc(Ahi, Alo, Bhi, Blo, h2, B_SZ, HD, 512, 4, 1);
    bias_softplus<<<1024, 256>>>(h2, b2_cn, B_SZ, HD);

    conv_pad<<<1024, 256>>>(h2, Ahi, Alo, B_SZ, HD, 512);
    tconv<<<dim3(4, 16), tb>>>(Wmu_cn, Bhi, Blo, HD, KT, 512);
    tconv<<<dim3(4, 16), tb>>>(Wlv_cn, Bhi + 100 * 512, Blo + 100 * 512, HD, KT, 512);
    zero_kernel<<<512, 256>>>(mulv, B_SZ * 200);
    launch_tc(Ahi, Alo, Bhi, Blo, mulv, B_SZ, 200, 512, 2, 1);
    theta_kl_kernel<<<B_SZ, 128>>>(mulv, bmu_cn, blv_cn, eps_cn, th_cn, theta_cn_out, acc + 3);

    // ================= topic norms =================
    rownorm2_kernel<<<(KT * 32 + 255) / 256, 256>>>(topic, tnm, KT, DE);

    // ================= beta EN + recon EN =================
    rownorm2_kernel<<<(NV_EN * 32 + 255) / 256, 256>>>(we_en, wn, NV_EN, DE);
    conv_pad<<<256, 256>>>(topic, Bhi, Blo, KT, DE, 320);          // topic is [N=100 x K=300] K-major already
    conv_pad<<<4096, 256>>>(we_en, Ahi, Alo, NV_EN, DE, 320);
    launch_tc(Ahi, Alo, Bhi, Blo, G, NV_EN, KT, 320, 1, 0);        // z=1: no split-K race on store
    zero_kernel<<<1, 128>>>(cs, KT);
    beta_pass1<<<(NV_EN + 255) / 256, 256>>>(G, wn, tnm, beta, cs, NV_EN);
    beta_pass2<<<2048, 256>>>(beta, beta_en_out, cs, NV_EN);
    tconv<<<dim3(938, 4), tb>>>(beta, Bhi, Blo, KT, NV_EN, 128);   // beta^T [V x 128]
    conv_pad<<<256, 256>>>(th_en, Ahi, Alo, B_SZ, KT, 128);
    launch_tc(Ahi, Alo, Bhi, Blo, recon, B_SZ, NV_EN, 128, 1, 0);
    recon_loss_kernel<<<B_SZ, 256>>>(x_en, recon, NV_EN, acc + 0);

    // ================= beta CN + recon CN =================
    rownorm2_kernel<<<(NV_CN * 32 + 255) / 256, 256>>>(we_cn, wn, NV_CN, DE);
    conv_pad<<<256, 256>>>(topic, Bhi, Blo, KT, DE, 320);
    conv_pad<<<4096, 256>>>(we_cn, Ahi, Alo, NV_CN, DE, 320);
    launch_tc(Ahi, Alo, Bhi, Blo, G, NV_CN, KT, 320, 1, 0);        // z=1: no split-K race on store
    zero_kernel<<<1, 128>>>(cs, KT);
    beta_pass1<<<(NV_CN + 255) / 256, 256>>>(G, wn, tnm, beta, cs, NV_CN);
    beta_pass2<<<2048, 256>>>(beta, beta_cn_out, cs, NV_CN);
    tconv<<<dim3(626, 4), tb>>>(beta, Bhi, Blo, KT, NV_CN, 128);
    conv_pad<<<256, 256>>>(th_cn, Ahi, Alo, B_SZ, KT, 128);
    launch_tc(Ahi, Alo, Bhi, Blo, recon, B_SZ, NV_CN, 128, 1, 0);
    recon_loss_kernel<<<B_SZ, 256>>>(x_cn, recon, NV_CN, acc + 2);

    // ================= contrastive =================
    select_norm_kernel<<<B_SZ, 128>>>(th_en, th_cn, tnb);
    contrast_kernel<<<B_SZ, 256>>>(tnb, cid, acc);

    // ================= alignment =================
    norm_topic_kernel<<<KT, 128>>>(topic, tnT);
    cmat_kernel<<<KT, 128>>>(tnT, Cm);
    sinkhorn_kernel<<<1, 256>>>(Cm, acc);

    finalize_kernel<<<1, 1>>>(acc, out);
}